// round 17
// baseline (speedup 1.0000x reference)
#include <cuda_runtime.h>
#include <math.h>

#define NB 128
#define NT 256
#define NE 300
#define NEP 320     // padded embedding K (zero-fill)
#define NH 512
#define NG 2048     // 4*NH
#define NC 11
#define TSTART 9
#define TSTOP 10
#define NEGV -100000.0f
#define MROWS (NB*NT)   // 32768
#define NBLK 128        // persistent grid size
#define NV 50000

// ---------------- scratch (static device memory; no allocations) ----------------
__device__ unsigned g_gxbf_f[(size_t)MROWS * (NG / 2)];  // fwd input projection, bf16x2
__device__ unsigned g_gxbf_r[(size_t)MROWS * (NG / 2)];  // bwd input projection, bf16x2
__device__ unsigned g_outbf0[(size_t)MROWS * (NH)];   // layer0 out, bf16x2
__device__ unsigned g_outbf1[(size_t)MROWS * (NH)];   // layer1 out, bf16x2
__device__ unsigned g_hbf[2 * 2 * NB * (NH / 2)]; // ping-pong h, packed bf16x2
__device__ unsigned g_embbf[(size_t)NV * (NEP / 2)];  // bf16x2 embedding table, padded
__device__ unsigned g_wbf0[2][(size_t)NG * (NEP / 2)];   // bf16x2 w_ih l0 / l0r
__device__ unsigned g_wbf1[2][(size_t)NG * (2 * NH / 2)];// bf16x2 w_ih l1 / l1r
__device__ float g_emis[(size_t)MROWS * NC];
__device__ unsigned char g_bt[(size_t)MROWS * NC];
__device__ float g_lossb[NB];

// ---------------- two-level tree barrier with replicated gen lines --------------
// Arrivals identical to R10-proven. Wake: gen replicated on 4 lines per group;
// waiter polls line (leaf&3) -> 16 pollers per L2 line instead of 64.
__device__ unsigned g_leafc[8 * 32];
__device__ unsigned g_rootc[2 * 32];
__device__ volatile unsigned g_genv[2 * 4 * 32];     // [grp][line][pad]

__global__ void reset_bar()
{
    int i = threadIdx.x;
    if (i < 256) ((unsigned*)g_leafc)[i] = 0u;
    if (i < 64)  ((unsigned*)g_rootc)[i] = 0u;
    if (i < 256) ((unsigned*)g_genv)[i]  = 0u;
}

__device__ __forceinline__ void bar_arrive(int grp, int leaf)
{
    __syncthreads();
    if (threadIdx.x == 0) {
        __threadfence();
        unsigned p = atomicAdd(&g_leafc[leaf * 32], 1u);
        if ((p & 15u) == 15u) {
            unsigned q = atomicAdd(&g_rootc[grp * 32], 1u);
            if ((q & 3u) == 3u) {
                __threadfence();
                unsigned g = (q >> 2) + 1u;
#pragma unroll
                for (int l = 0; l < 4; l++)
                    g_genv[(grp * 4 + l) * 32] = g;
            }
        }
    }
}

__device__ __forceinline__ void bar_wait(int grp, int line, unsigned my)
{
    if (threadIdx.x == 0) {
        while (g_genv[(grp * 4 + line) * 32] <= my) { }
    }
    __syncthreads();
    // no post-wake fence: cross-block data (h) is read via cp.async.cg (L2-direct).
}

// ---------------- numeric helpers -----------------------------------------------
__device__ __forceinline__ unsigned pack_bf16x2(float lo, float hi)
{
    unsigned r;
    asm("cvt.rn.bf16x2.f32 %0, %1, %2;" : "=r"(r) : "f"(hi), "f"(lo));
    return r;
}

__device__ __forceinline__ void mma_bf16(float* d, const unsigned* a, const unsigned* b)
{
    asm volatile(
        "mma.sync.aligned.m16n8k16.row.col.f32.bf16.bf16.f32 "
        "{%0,%1,%2,%3}, {%4,%5,%6,%7}, {%8,%9}, {%0,%1,%2,%3};\n"
        : "+f"(d[0]), "+f"(d[1]), "+f"(d[2]), "+f"(d[3])
        : "r"(a[0]), "r"(a[1]), "r"(a[2]), "r"(a[3]), "r"(b[0]), "r"(b[1]));
}

// ---------------- conversion kernels (run each replay; deterministic) -----------
__global__ void conv_emb(const float* __restrict__ emb)
{
    size_t i = (size_t)blockIdx.x * 256 + threadIdx.x;
    if (i >= (size_t)NV * (NEP / 2)) return;
    int c2  = (int)(i % (NEP / 2));
    size_t row = i / (NEP / 2);
    int c = 2 * c2;
    float lo = (c < NE)     ? emb[row * NE + c]     : 0.f;
    float hi = (c + 1 < NE) ? emb[row * NE + c + 1] : 0.f;
    g_embbf[i] = pack_bf16x2(lo, hi);
}

__global__ void conv_w(const float* __restrict__ W, unsigned* __restrict__ dst,
                       int K, int Kp2)
{
    size_t i = (size_t)blockIdx.x * 256 + threadIdx.x;
    if (i >= (size_t)NG * Kp2) return;
    int c2  = (int)(i % Kp2);
    size_t row = i / Kp2;
    int c = 2 * c2;
    float lo = (c < K)     ? W[row * K + c]     : 0.f;
    float hi = (c + 1 < K) ? W[row * K + c + 1] : 0.f;
    dst[i] = pack_bf16x2(lo, hi);
}

// ---------------- bf16 gx GEMM; epilogue packs bf16x2 ---------------------------
#define GXS 20   // row stride in u32 (16 used = 32 bf16 k)
__global__ __launch_bounds__(256) void gx_gemm_bf16(
    const int* __restrict__ tokens,
    const unsigned* __restrict__ Wb0, const float* __restrict__ bi0, const float* __restrict__ bh0,
    const unsigned* __restrict__ Wb1, const float* __restrict__ bi1, const float* __restrict__ bh1,
    int Kp2, int gather)
{
    int dir = blockIdx.z;
    const unsigned* W = dir ? Wb1 : Wb0;
    const float* bi = dir ? bi1 : bi0;
    const float* bh = dir ? bh1 : bh0;
    unsigned* out = dir ? g_gxbf_r : g_gxbf_f;

    __shared__ unsigned As[2][128 * GXS];
    __shared__ unsigned Bs[2][128 * GXS];

    int tid  = threadIdx.x;
    int warp = tid >> 5;
    int lane = tid & 31;
    int quad = lane >> 2;
    int l4   = lane & 3;
    int wm   = (warp >> 1) * 32;
    int wn   = (warp & 1) * 64;

    int m0 = blockIdx.y * 128;
    int n0 = blockIdx.x * 128;

    float acc[2][8][4];
#pragma unroll
    for (int i = 0; i < 2; i++)
#pragma unroll
        for (int j = 0; j < 8; j++)
#pragma unroll
            for (int q = 0; q < 4; q++) acc[i][j][q] = 0.f;

    int kiters = Kp2 >> 4;

    auto do_stage = [&](int buf, int kt) {
        int k2_0 = kt << 4;
#pragma unroll
        for (int r = 0; r < 2; r++) {
            int f  = tid + 256 * r;
            int mm = f >> 2;
            int sg = (f & 3) * 4;
            int row = m0 + mm;
            const unsigned* src = gather
                ? (g_embbf + (size_t)tokens[row] * (NEP / 2) + k2_0 + sg)
                : (g_outbf0 + (size_t)row * NH + k2_0 + sg);
            unsigned d = (unsigned)__cvta_generic_to_shared(&As[buf][mm * GXS + sg]);
            asm volatile("cp.async.cg.shared.global [%0], [%1], 16;" :: "r"(d), "l"(src));
        }
#pragma unroll
        for (int r = 0; r < 2; r++) {
            int f  = tid + 256 * r;
            int nn = f >> 2;
            int sg = (f & 3) * 4;
            const unsigned* src = W + (size_t)(n0 + nn) * Kp2 + k2_0 + sg;
            unsigned d = (unsigned)__cvta_generic_to_shared(&Bs[buf][nn * GXS + sg]);
            asm volatile("cp.async.cg.shared.global [%0], [%1], 16;" :: "r"(d), "l"(src));
        }
        asm volatile("cp.async.commit_group;");
    };

    do_stage(0, 0);

    for (int kt = 0; kt < kiters; kt++) {
        int buf = kt & 1;
        if (kt + 1 < kiters) {
            do_stage(buf ^ 1, kt + 1);
            asm volatile("cp.async.wait_group 1;");
        } else {
            asm volatile("cp.async.wait_group 0;");
        }
        __syncthreads();

        const unsigned* Ab = As[buf];
        const unsigned* Bb = Bs[buf];
#pragma unroll
        for (int kg = 0; kg < 16; kg += 8) {
            unsigned a[2][4], b[8][2];
#pragma unroll
            for (int mt = 0; mt < 2; mt++) {
                int mb = wm + mt * 16;
                a[mt][0] = Ab[(mb + quad) * GXS + kg + l4];
                a[mt][1] = Ab[(mb + quad + 8) * GXS + kg + l4];
                a[mt][2] = Ab[(mb + quad) * GXS + kg + l4 + 4];
                a[mt][3] = Ab[(mb + quad + 8) * GXS + kg + l4 + 4];
            }
#pragma unroll
            for (int nt = 0; nt < 8; nt++) {
                int nb = wn + nt * 8;
                b[nt][0] = Bb[(nb + quad) * GXS + kg + l4];
                b[nt][1] = Bb[(nb + quad) * GXS + kg + l4 + 4];
            }
#pragma unroll
            for (int mt = 0; mt < 2; mt++)
#pragma unroll
                for (int nt = 0; nt < 8; nt++)
                    mma_bf16(acc[mt][nt], a[mt], b[nt]);
        }
        __syncthreads();
    }

#pragma unroll
    for (int mt = 0; mt < 2; mt++) {
        int r0 = m0 + wm + mt * 16 + quad;
#pragma unroll
        for (int nt = 0; nt < 8; nt++) {
            int col = n0 + wn + nt * 8 + l4 * 2;     // even
            float bsum0 = bi[col] + bh[col];
            float bsum1 = bi[col + 1] + bh[col + 1];
            out[(size_t)r0 * (NG / 2) + (col >> 1)] =
                pack_bf16x2(acc[mt][nt][0] + bsum0, acc[mt][nt][1] + bsum1);
            out[(size_t)(r0 + 8) * (NG / 2) + (col >> 1)] =
                pack_bf16x2(acc[mt][nt][2] + bsum0, acc[mt][nt][3] + bsum1);
        }
    }
}

// ---------------- bf16 persistent bidirectional LSTM, 8-deep h pipeline ---------
#define WSS2 40
#define HSS2 36
#define WS2_U (256 * WSS2)      // 10240 u32
#define HS2_U (NB * HSS2)       // 4608 u32 per chunk buffer
#define LSTM_SMEM ((WS2_U + 8 * HS2_U) * 4)   // 188416 bytes

__device__ __forceinline__ void stage_chunk(const unsigned* __restrict__ hsrc,
                                            unsigned* __restrict__ dstbase,
                                            int chunk, int tid)
{
#pragma unroll
    for (int r = 0; r < 4; r++) {
        int f   = tid + 256 * r;
        int row = f >> 3;
        int seg = f & 7;
        unsigned daddr = (unsigned)__cvta_generic_to_shared(dstbase + row * HSS2 + seg * 4);
        const unsigned* src = hsrc + row * (NH / 2) + chunk * 32 + seg * 4;
        asm volatile("cp.async.cg.shared.global [%0], [%1], 16;" :: "r"(daddr), "l"(src));
    }
}

__device__ __forceinline__ void wait_groups_leq(int n)
{
    switch (n) {
        case 0: asm volatile("cp.async.wait_group 0;"); break;
        case 1: asm volatile("cp.async.wait_group 1;"); break;
        case 2: asm volatile("cp.async.wait_group 2;"); break;
        case 3: asm volatile("cp.async.wait_group 3;"); break;
        case 4: asm volatile("cp.async.wait_group 4;"); break;
        case 5: asm volatile("cp.async.wait_group 5;"); break;
        case 6: asm volatile("cp.async.wait_group 6;"); break;
        default: asm volatile("cp.async.wait_group 7;"); break;
    }
}

__global__ __launch_bounds__(256) void lstm_persist_tc(
    const int* __restrict__ seq_len,
    const float* __restrict__ Whf, const float* __restrict__ Whr,
    int layer)
{
    extern __shared__ unsigned usmem[];
    unsigned* Wsm = usmem;
    unsigned* hsb = usmem + WS2_U;      // 8 chunk buffers, HS2_U apart

    int tid  = threadIdx.x;
    int bid  = blockIdx.x;
    int dir  = bid >> 6;
    int hc0  = (bid & 63) * 8;
    int grp  = dir;
    int leaf = bid >> 4;
    int pline = leaf & 3;               // replicated gen line

    int w    = tid >> 5;
    int lane = tid & 31;
    int quad = lane >> 2;
    int l4   = lane & 3;

    const float* W   = dir ? Whr : Whf;
    const unsigned* gxp = dir ? g_gxbf_r : g_gxbf_f;
    unsigned* outp = layer ? g_outbf1 : g_outbf0;

    unsigned gen = g_genv[(grp * 4 + pline) * 32];

    for (int jj = tid; jj < 32 * 256; jj += 256) {
        int c = jj >> 8, k2 = jj & 255;
        int g = c >> 3, j = c & 7;
        const float* wr = W + (size_t)(g * NH + hc0 + j) * NH + 2 * k2;
        Wsm[k2 * WSS2 + c] = pack_bf16x2(wr[0], wr[1]);
    }

#pragma unroll
    for (int i = 0; i < 2; i++)
        g_hbf[bid * 512 + i * 256 + tid] = 0u;

    int b0 = 16 * w + quad;
    int b1 = b0 + 8;
    int hhbase = hc0 + 2 * l4;          // even
    int hc2 = hhbase >> 1;              // u32 col within gate block
    int sl0 = seq_len[b0];
    int sl1 = seq_len[b1];
    float c_reg[4] = {0.f, 0.f, 0.f, 0.f};
    float h_reg[4] = {0.f, 0.f, 0.f, 0.f};

    float gxv[4][4];
    auto load_gx = [&](int t_data) {
        size_t base0 = (size_t)(b0 * NT + t_data) * (NG / 2) + hc2;
        size_t base1 = (size_t)(b1 * NT + t_data) * (NG / 2) + hc2;
#pragma unroll
        for (int g = 0; g < 4; g++) {
            unsigned p0 = gxp[base0 + g * (NH / 2)];
            unsigned p1 = gxp[base1 + g * (NH / 2)];
            gxv[g][0] = __uint_as_float(p0 << 16);
            gxv[g][1] = __uint_as_float(p0 & 0xffff0000u);
            gxv[g][2] = __uint_as_float(p1 << 16);
            gxv[g][3] = __uint_as_float(p1 & 0xffff0000u);
        }
    };
    load_gx(dir ? (NT - 1) : 0);

    bar_arrive(grp, leaf);
    bar_wait(grp, pline, gen); gen++;

    for (int t = 0; t < NT; t++) {
        int rb = t & 1;
        int wbuf = 1 - rb;
        int t_data = dir ? (NT - 1 - t) : t;

        const unsigned* hsrc = g_hbf + rb * (2 * NB * (NH / 2)) + dir * (NB * (NH / 2));

        // stage ALL 8 chunks immediately after wake
#pragma unroll
        for (int c = 0; c < 8; c++) {
            stage_chunk(hsrc, hsb + c * HS2_U, c, tid);
            asm volatile("cp.async.commit_group;");
        }

        float acc[4][4];
#pragma unroll
        for (int g = 0; g < 4; g++)
#pragma unroll
            for (int q = 0; q < 4; q++) acc[g][q] = 0.f;

#pragma unroll
        for (int chunk = 0; chunk < 8; chunk++) {
            wait_groups_leq(7 - chunk);
            __syncthreads();

            const unsigned* cur = hsb + chunk * HS2_U;
            int k2g0 = chunk * 32;
#pragma unroll
            for (int s = 0; s < 4; s++) {
                int k2c = s * 8;
                unsigned a[4];
                a[0] = cur[b0 * HSS2 + k2c + l4];
                a[1] = cur[b1 * HSS2 + k2c + l4];
                a[2] = cur[b0 * HSS2 + k2c + l4 + 4];
                a[3] = cur[b1 * HSS2 + k2c + l4 + 4];
                int k2g = k2g0 + k2c;
#pragma unroll
                for (int g = 0; g < 4; g++) {
                    unsigned b[2];
                    b[0] = Wsm[(k2g + l4) * WSS2 + g * 8 + quad];
                    b[1] = Wsm[(k2g + l4 + 4) * WSS2 + g * 8 + quad];
                    mma_bf16(acc[g], a, b);
                }
            }
        }
        __syncthreads();

        unsigned* hdst = g_hbf + wbuf * (2 * NB * (NH / 2)) + dir * (NB * (NH / 2));
        bool mt0 = t_data < sl0;
        bool mt1 = t_data < sl1;
        float hout[4];
#pragma unroll
        for (int k = 0; k < 4; k++) {
            int r  = k >> 1;
            float gi = acc[0][k] + gxv[0][k];
            float gf = acc[1][k] + gxv[1][k];
            float gg = acc[2][k] + gxv[2][k];
            float go = acc[3][k] + gxv[3][k];

            float iv = 1.f / (1.f + expf(-gi));
            float fv = 1.f / (1.f + expf(-gf));
            float ov = 1.f / (1.f + expf(-go));
            float gv = tanhf(gg);

            float cn = fv * c_reg[k] + iv * gv;
            float hn = ov * tanhf(cn);

            bool mt = r ? mt1 : mt0;
            if (mt) { c_reg[k] = cn; h_reg[k] = hn; }
            hout[k] = mt ? hn : 0.f;
        }
        hdst[b0 * (NH / 2) + hc2] = pack_bf16x2(h_reg[0], h_reg[1]);
        hdst[b1 * (NH / 2) + hc2] = pack_bf16x2(h_reg[2], h_reg[3]);

        bar_arrive(grp, leaf);

        // hidden in the poll window: packed outp stores + next-step gx prefetch
        {
            int oc = (dir * NH + hhbase) >> 1;
            outp[(size_t)(b0 * NT + t_data) * NH + oc] = pack_bf16x2(hout[0], hout[1]);
            outp[(size_t)(b1 * NT + t_data) * NH + oc] = pack_bf16x2(hout[2], hout[3]);
        }
        if (t + 1 < NT) {
            load_gx(dir ? (NT - 2 - t) : (t + 1));
        }

        bar_wait(grp, pline, gen); gen++;
    }
}

// ---------------- emission FC (bf16 inputs) -------------------------------------
__global__ void emis_kernel(const float* __restrict__ fw, const float* __restrict__ fb)
{
    int gtid = blockIdx.x * blockDim.x + threadIdx.x;
    int w = gtid >> 5;
    int lane = threadIdx.x & 31;
    if (w >= MROWS) return;
    const unsigned* x = g_outbf1 + (size_t)w * NH;
    float acc[NC];
#pragma unroll
    for (int c = 0; c < NC; c++) acc[c] = 0.f;
    for (int k2 = lane; k2 < NH; k2 += 32) {
        unsigned p = x[k2];
        float lo = __uint_as_float(p << 16);
        float hi = __uint_as_float(p & 0xffff0000u);
        int k = 2 * k2;
#pragma unroll
        for (int c = 0; c < NC; c++)
            acc[c] += lo * fw[c * 2 * NH + k] + hi * fw[c * 2 * NH + k + 1];
    }
#pragma unroll
    for (int off = 16; off > 0; off >>= 1)
#pragma unroll
        for (int c = 0; c < NC; c++) acc[c] += __shfl_down_sync(0xffffffffu, acc[c], off);
    if (lane == 0) {
#pragma unroll
        for (int c = 0; c < NC; c++) g_emis[(size_t)w * NC + c] = acc[c] + fb[c];
    }
}

// ---------------- CRF -----------------------------------------------------------
__global__ void crf_kernel(const int* __restrict__ seq_len, const int* __restrict__ tags,
                           const float* __restrict__ trans, float* __restrict__ out)
{
    int b = blockIdx.x;
    int lane = threadIdx.x;
    __shared__ float tr[NC][NC + 1];
    __shared__ float vs[NC + 1], fs[NC + 1], vf[NC + 1], ff[NC + 1];

    for (int i = lane; i < NC * NC; i += 32) tr[i / NC][i % NC] = trans[i];
    if (lane < NC) { vs[lane] = 0.f; fs[lane] = NEGV; }
    __syncwarp();

    int sl = seq_len[b];
    for (int t = 0; t < NT; t++) {
        float vnew = 0.f, fnew = 0.f;
        if (lane < NC) {
            float emi = g_emis[(size_t)(b * NT + t) * NC + lane];
            float best = vs[0] + tr[0][lane]; int bi = 0;
            float m = fs[0] + tr[0][lane];
#pragma unroll
            for (int i = 1; i < NC; i++) {
                float v = vs[i] + tr[i][lane];
                if (v > best) { best = v; bi = i; }
                float fv = fs[i] + tr[i][lane];
                if (fv > m) m = fv;
            }
            float s = 0.f;
#pragma unroll
            for (int i = 0; i < NC; i++) s += expf(fs[i] + tr[i][lane] - m);
            vnew = best + emi;
            fnew = emi + m + logf(s);
            g_bt[(size_t)(b * NT + t) * NC + lane] = (unsigned char)bi;
        }
        __syncwarp();
        if (lane < NC && t < sl) { vs[lane] = vnew; fs[lane] = fnew; }
        __syncwarp();
    }
    if (lane < NC) {
        vf[lane] = vs[lane] + tr[lane][TSTOP];
        ff[lane] = fs[lane] + tr[lane][TSTOP];
    }
    __syncwarp();
    if (lane == 0) {
        int best = 0; float bv = vf[0];
        for (int j = 1; j < NC; j++) if (vf[j] > bv) { bv = vf[j]; best = j; }
        float m = ff[0];
        for (int j = 1; j < NC; j++) if (ff[j] > m) m = ff[j];
        float s = 0.f;
        for (int j = 0; j < NC; j++) s += expf(ff[j] - m);
        float fwd = m + logf(s);

        float gold = 0.f; int prev = TSTART;
        for (int t = 0; t < sl; t++) {
            int tg = tags[b * NT + t];
            gold += g_emis[(size_t)(b * NT + t) * NC + tg] + tr[prev][tg];
            prev = tg;
        }
        gold += tr[prev][TSTOP];
        g_lossb[b] = fwd - gold;

        int cur = best;
        for (int l = NT - 1; l >= 0; l--) {
            out[b * NT + l] = (l < sl) ? (float)cur : 0.f;
            if (l >= 1 && l <= sl - 1) cur = g_bt[(size_t)(b * NT + l) * NC + cur];
        }
    }
}

__global__ void loss_reduce(float* __restrict__ out)
{
    __shared__ float s[NB];
    int i = threadIdx.x;
    s[i] = g_lossb[i];
    __syncthreads();
    for (int off = NB / 2; off > 0; off >>= 1) {
        if (i < off) s[i] += s[i + off];
        __syncthreads();
    }
    if (i == 0) out[MROWS] = s[0] / (float)NB;
}

// ---------------- launcher ------------------------------------------------------
extern "C" void kernel_launch(void* const* d_in, const int* in_sizes, int n_in,
                              void* d_out, int out_size)
{
    const int*   tokens   = (const int*)d_in[0];
    const int*   seq_len  = (const int*)d_in[1];
    const int*   tags     = (const int*)d_in[3];
    const float* emb      = (const float*)d_in[4];
    const float* w_ih_l0  = (const float*)d_in[5];
    const float* w_hh_l0  = (const float*)d_in[6];
    const float* b_ih_l0  = (const float*)d_in[7];
    const float* b_hh_l0  = (const float*)d_in[8];
    const float* w_ih_l0r = (const float*)d_in[9];
    const float* w_hh_l0r = (const float*)d_in[10];
    const float* b_ih_l0r = (const float*)d_in[11];
    const float* b_hh_l0r = (const float*)d_in[12];
    const float* w_ih_l1  = (const float*)d_in[13];
    const float* w_hh_l1  = (const float*)d_in[14];
    const float* b_ih_l1  = (const float*)d_in[15];
    const float* b_hh_l1  = (const float*)d_in[16];
    const float* w_ih_l1r = (const float*)d_in[17];
    const float* w_hh_l1r = (const float*)d_in[18];
    const float* b_ih_l1r = (const float*)d_in[19];
    const float* b_hh_l1r = (const float*)d_in[20];
    const float* fc_w     = (const float*)d_in[21];
    const float* fc_b     = (const float*)d_in[22];
    const float* trans    = (const float*)d_in[23];
    float* out = (float*)d_out;

    static int smem_set = 0;
    if (!smem_set) {
        cudaFuncSetAttribute(lstm_persist_tc,
                             cudaFuncAttributeMaxDynamicSharedMemorySize, LSTM_SMEM);
        smem_set = 1;
    }

    unsigned* wbf0_0; cudaGetSymbolAddress((void**)&wbf0_0, g_wbf0);
    unsigned* wbf1_0; cudaGetSymbolAddress((void**)&wbf1_0, g_wbf1);
    unsigned* wbf0_1 = wbf0_0 + (size_t)NG * (NEP / 2);
    unsigned* wbf1_1 = wbf1_0 + (size_t)NG * NH;

    // ---- convert embedding table + input-projection weights to bf16 ----
    {
        size_t n_emb = (size_t)NV * (NEP / 2);
        conv_emb<<<(unsigned)((n_emb + 255) / 256), 256>>>(emb);
        size_t n_w0 = (size_t)NG * (NEP / 2);
        conv_w<<<(unsigned)((n_w0 + 255) / 256), 256>>>(w_ih_l0,  wbf0_0, NE, NEP / 2);
        conv_w<<<(unsigned)((n_w0 + 255) / 256), 256>>>(w_ih_l0r, wbf0_1, NE, NEP / 2);
        size_t n_w1 = (size_t)NG * NH;
        conv_w<<<(unsigned)((n_w1 + 255) / 256), 256>>>(w_ih_l1,  wbf1_0, 2 * NH, NH);
        conv_w<<<(unsigned)((n_w1 + 255) / 256), 256>>>(w_ih_l1r, wbf1_1, 2 * NH, NH);
    }

    reset_bar<<<1, 256>>>();

    dim3 ggx(NG / 128, MROWS / 128, 2);

    // ---- layer 0 ----
    gx_gemm_bf16<<<ggx, 256>>>(tokens,
                               wbf0_0, b_ih_l0, b_hh_l0,
                               wbf0_1, b_ih_l0r, b_hh_l0r, NEP / 2, 1);
    lstm_persist_tc<<<NBLK, 256, LSTM_SMEM>>>(seq_len, w_hh_l0, w_hh_l0r, 0);

    // ---- layer 1 ----
    gx_gemm_bf16<<<ggx, 256>>>(tokens,
                               wbf1_0, b_ih_l1, b_hh_l1,
                               wbf1_1, b_ih_l1r, b_hh_l1r, NH, 0);
    lstm_persist_tc<<<NBLK, 256, LSTM_SMEM>>>(seq_len, w_hh_l1, w_hh_l1r, 1);

    // ---- emissions + CRF ----
    emis_kernel<<<MROWS / 8, 256>>>(fc_w, fc_b);
    crf_kernel<<<NB, 32>>>(seq_len, tags, trans, out);
    loss_reduce<<<1, 128>>>(out);
}